// round 15
// baseline (speedup 1.0000x reference)
#include <cuda_runtime.h>
#include <cstdint>
#include <math.h>

#define B    16
#define H    512
#define V    32000
#define NL   2
#define NBLK 128           // persistent blocks, 1/SM, all co-resident
#define NTHR 512           // 16 warps/SM
#define ROWS_PER_BLK 250   // 128 * 250 = 32000 = V
#define RPAIRS 125         // row pairs per block
#define WCHUNK 32          // logits K-chunk (floats)
#define NCHUNK (H / WCHUNK)        // 16
#define WPADF  36          // padded row floats = 9 x 16B (odd) -> conflict-free
#define WTILEF (ROWS_PER_BLK * WPADF)   // 9000 floats per buffer

typedef unsigned long long u64;

// dyn smem layout (floats):
//  LSTM : s_in = [0,8192), s_h = [8192,16384)
//  logit: h_s  = [0,8192), W_s = [16384, 16384 + 2*9000)
#define DYN_FLOATS (16384 + 2 * WTILEF)
#define SMEM_BYTES (DYN_FLOATS * 4)

// ---------------- device state ----------------
__device__ float g_h[2][NL][B][H];     // ping-pong hidden state
__device__ u64 g_amax[2][B];           // double-buffered argmax accumulator
__device__ unsigned g_cnt;             // monotonic barrier counter

// ---------------- packed f32x2 helpers ----------------
__device__ __forceinline__ u64 fma2(u64 a, u64 b, u64 c) {
    u64 d; asm("fma.rn.f32x2 %0,%1,%2,%3;" : "=l"(d) : "l"(a), "l"(b), "l"(c));
    return d;
}
__device__ __forceinline__ u64 add2(u64 a, u64 b) {
    u64 d; asm("add.rn.f32x2 %0,%1,%2;" : "=l"(d) : "l"(a), "l"(b));
    return d;
}
__device__ __forceinline__ float2 unpk(u64 a) {
    float2 r; asm("mov.b64 {%0,%1},%2;" : "=f"(r.x), "=f"(r.y) : "l"(a));
    return r;
}
__device__ __forceinline__ float sigm(float x) { return 1.f / (1.f + expf(-x)); }

// ---------------- cp.async helpers ----------------
__device__ __forceinline__ void cpa16(uint32_t dst, const void* src) {
    asm volatile("cp.async.cg.shared.global [%0], [%1], 16;"
                 :: "r"(dst), "l"(src));
}
#define CP_COMMIT() asm volatile("cp.async.commit_group;")
#define CP_WAIT0()  asm volatile("cp.async.wait_group 0;")

// ---------------- grid barrier: release-add / acquire-spin, one address ----
__device__ __forceinline__ void gbar(unsigned target) {
    __syncthreads();
    if (threadIdx.x == 0) {
        asm volatile("red.release.gpu.global.add.u32 [%0], 1;"
                     :: "l"(&g_cnt) : "memory");
        const unsigned need = NBLK * target;
        unsigned v;
        for (;;) {
            asm volatile("ld.acquire.gpu.global.u32 %0, [%1];"
                         : "=r"(v) : "l"(&g_cnt) : "memory");
            if (v >= need) break;
            __nanosleep(64);                   // backoff: cut poll traffic
        }
    }
    __syncthreads();
}

// ---------------- init ----------------
__global__ void init_kernel() {
    int tid = blockIdx.x * blockDim.x + threadIdx.x;
    int stride = gridDim.x * blockDim.x;
    float* p = &g_h[0][0][0][0];
    for (int i = tid; i < 2 * NL * B * H; i += stride) p[i] = 0.f;
    if (blockIdx.x == 0 && threadIdx.x < 2 * B)
        (&g_amax[0][0])[threadIdx.x] = 0ull;
    if (blockIdx.x == 0 && threadIdx.x == 0) g_cnt = 0u;
}

// ---------------- persistent decoder ----------------
__global__ __launch_bounds__(NTHR, 1) void decoder_kernel(
    const float* __restrict__ x,   const float* __restrict__ Wt,
    const float* __restrict__ bp,  const float* __restrict__ Wih,
    const float* __restrict__ Whh, const float* __restrict__ bih,
    const float* __restrict__ bhh, float* __restrict__ out, int T)
{
    extern __shared__ __align__(16) float dyn[];
    __shared__ float s_part[2][2][4][4][8];   // [side][bhalf][jl][gate][b8]
    __shared__ u64 s_best[B][16];

    const int tid  = threadIdx.x;
    const int bx   = blockIdx.x;
    const int lane = tid & 31;
    const int warp = tid >> 5;

    // ---- LSTM role: warp = (side, bhalf, jl) ----
    const int w_jl    = warp & 3;
    const int w_bh    = (warp >> 2) & 1;
    const int w_side  = warp >> 3;
    const int j       = bx * 4 + w_jl;        // 0..511

    // ---- logits role: thread = (row-pair rp, batch-quad bq) ----
    // 2 rows x 4 batches register tile -> W and h LDS both lane-dedup'd.
    const int v0     = bx * ROWS_PER_BLK;
    const int rp_raw = tid >> 2;              // 0..127
    const bool vact  = (rp_raw < RPAIRS);
    const int rp     = vact ? rp_raw : (RPAIRS - 1);   // clamp: uniform, in-bounds
    const int bq     = tid & 3;               // batches bq*4 .. bq*4+3

    float* const s_in = dyn;                  // [16][512]
    float* const s_h  = dyn + 8192;           // [16][512]
    float* const h_s  = dyn;                  // [16][512] (logits phase)
    float* const W_s  = dyn + 16384;          // [2][250][36]

    float c_reg[2] = {0.f, 0.f};              // cell state, fixed per thread
    unsigned target = 0;

#pragma unroll 1
    for (int t = 0; t < T; t++) {
        const int p = t & 1;                  // h read side; write side 1-p

        // ================= LSTM layers =================
#pragma unroll
        for (int layer = 0; layer < NL; layer++) {
            // ---- stage input + recurrent h for ALL 16 batches ----
            for (int i = tid; i < 2048; i += NTHR) {
                int b = i >> 7, c4 = i & 127;
                const float4* srcp;
                if (layer == 0) {
                    if (t == 0) {
                        srcp = (const float4*)(x + (size_t)b * H) + c4;
                    } else {
                        u64 am;
                        asm volatile("ld.global.cg.u64 %0,[%1];"
                                     : "=l"(am) : "l"(&g_amax[1 - p][b])
                                     : "memory");
                        unsigned idx = ~(unsigned)am;
                        if (idx >= V) idx = 0;          // defensive
                        srcp = (const float4*)(Wt + (size_t)idx * H) + c4;
                    }
                } else {
                    srcp = (const float4*)(&g_h[1 - p][0][b][0]) + c4;
                }
                ((float4*)s_in)[i] = __ldcg(srcp);
                ((float4*)s_h)[i] =
                    __ldcg((const float4*)(&g_h[p][layer][b][0]) + c4);
            }
            __syncthreads();

            // ---- partial dot: 4 gates x 8 batches, one W-side per warp ----
            const float* Wsel = (w_side ? Whh : Wih) + (size_t)layer * 4 * H * H;
            const float* ssel = (w_side ? s_h : s_in) + (w_bh << 3) * H;

            u64 acc[4][8];
#pragma unroll
            for (int g = 0; g < 4; g++)
#pragma unroll
                for (int b8 = 0; b8 < 8; b8++) acc[g][b8] = 0ull;

#pragma unroll
            for (int c = 0; c < 4; c++) {
                const int koff = c * 128 + lane * 4;
                // weight rows stay hot in L1 across steps (persistent kernel)
                ulonglong2 w0 = *(const ulonglong2*)(Wsel + (size_t)(0 * H + j) * H + koff);
                ulonglong2 w1 = *(const ulonglong2*)(Wsel + (size_t)(1 * H + j) * H + koff);
                ulonglong2 w2 = *(const ulonglong2*)(Wsel + (size_t)(2 * H + j) * H + koff);
                ulonglong2 w3 = *(const ulonglong2*)(Wsel + (size_t)(3 * H + j) * H + koff);
#pragma unroll
                for (int b8 = 0; b8 < 8; b8++) {
                    ulonglong2 sv = *(const ulonglong2*)(ssel + (b8 << 9) + koff);
                    acc[0][b8] = fma2(w0.x, sv.x, acc[0][b8]);
                    acc[0][b8] = fma2(w0.y, sv.y, acc[0][b8]);
                    acc[1][b8] = fma2(w1.x, sv.x, acc[1][b8]);
                    acc[1][b8] = fma2(w1.y, sv.y, acc[1][b8]);
                    acc[2][b8] = fma2(w2.x, sv.x, acc[2][b8]);
                    acc[2][b8] = fma2(w2.y, sv.y, acc[2][b8]);
                    acc[3][b8] = fma2(w3.x, sv.x, acc[3][b8]);
                    acc[3][b8] = fma2(w3.y, sv.y, acc[3][b8]);
                }
            }
            // ---- warp tree reduce (lane 0 gets the k-sum) ----
#pragma unroll
            for (int off = 16; off >= 1; off >>= 1) {
#pragma unroll
                for (int g = 0; g < 4; g++)
#pragma unroll
                    for (int b8 = 0; b8 < 8; b8++)
                        acc[g][b8] = add2(acc[g][b8],
                            __shfl_down_sync(0xffffffffu, acc[g][b8], off));
            }
            if (lane == 0) {
#pragma unroll
                for (int g = 0; g < 4; g++)
#pragma unroll
                    for (int b8 = 0; b8 < 8; b8++) {
                        float2 f = unpk(acc[g][b8]);
                        s_part[w_side][w_bh][w_jl][g][b8] = f.x + f.y;
                    }
            }
            __syncthreads();

            // ---- activations: tid<64 owns cell (layer, b, j2) ----
            if (tid < 64) {
                int b8a = tid & 7, jla = (tid >> 3) & 3, bha = tid >> 5;
                int b  = bha * 8 + b8a;
                int j2 = bx * 4 + jla;
                const float* bi = bih + (size_t)layer * 4 * H;
                const float* bh = bhh + (size_t)layer * 4 * H;
                float gi = s_part[0][bha][jla][0][b8a] + s_part[1][bha][jla][0][b8a]
                         + bi[0 * H + j2] + bh[0 * H + j2];
                float gf = s_part[0][bha][jla][1][b8a] + s_part[1][bha][jla][1][b8a]
                         + bi[1 * H + j2] + bh[1 * H + j2];
                float gg = s_part[0][bha][jla][2][b8a] + s_part[1][bha][jla][2][b8a]
                         + bi[2 * H + j2] + bh[2 * H + j2];
                float go = s_part[0][bha][jla][3][b8a] + s_part[1][bha][jla][3][b8a]
                         + bi[3 * H + j2] + bh[3 * H + j2];
                float cn = sigm(gf) * c_reg[layer] + sigm(gi) * tanhf(gg);
                float hn = sigm(go) * tanhf(cn);
                c_reg[layer] = cn;
                g_h[1 - p][layer][b][j2] = hn;
            }
            gbar(++target);
        }

        // ================= logits + argmax (reg-tiled, cp.async W) ==========
        {
            // reset the OTHER amax slot for step t+1
            if (bx == 0 && tid < B) atomicExch(&g_amax[1 - p][tid], 0ull);

            // prefetch W chunk 0 into buffer 0
            for (int idx = tid; idx < ROWS_PER_BLK * 8; idx += NTHR) {
                int row = idx >> 3, seg = idx & 7;
                cpa16((uint32_t)__cvta_generic_to_shared(
                          &W_s[row * WPADF + seg * 4]),
                      Wt + (size_t)(v0 + row) * H + seg * 4);
            }
            CP_COMMIT();

            // stage h1 [16][512] (overlaps with the cp.async above)
            const float4* hp = (const float4*)(&g_h[1 - p][1][0][0]);
            for (int i = tid; i < 2048; i += NTHR)
                ((float4*)h_s)[i] = __ldcg(hp + i);

            u64 acc[2][4];                     // [row-in-pair][batch-in-quad]
#pragma unroll
            for (int r = 0; r < 2; r++)
#pragma unroll
                for (int i = 0; i < 4; i++) acc[r][i] = 0ull;

#pragma unroll 1
            for (int kc = 0; kc < NCHUNK; kc++) {
                CP_WAIT0();
                __syncthreads();                 // chunk kc visible; prev done
                if (kc + 1 < NCHUNK) {           // prefetch kc+1 -> other buf
                    float* Wn = W_s + ((kc + 1) & 1) * WTILEF;
                    const float* gsrc = Wt + (size_t)v0 * H + (kc + 1) * WCHUNK;
                    for (int idx = tid; idx < ROWS_PER_BLK * 8; idx += NTHR) {
                        int row = idx >> 3, seg = idx & 7;
                        cpa16((uint32_t)__cvta_generic_to_shared(
                                  &Wn[row * WPADF + seg * 4]),
                              gsrc + (size_t)row * H + seg * 4);
                    }
                }
                CP_COMMIT();

                const float* W0 = W_s + (kc & 1) * WTILEF + (rp * 2) * WPADF;
                const float* W1 = W0 + WPADF;
                const float* hc = h_s + (bq << 2) * H + kc * WCHUNK;
#pragma unroll
                for (int q = 0; q < 8; q++) {
                    ulonglong2 w0 = *(const ulonglong2*)(W0 + q * 4);
                    ulonglong2 w1 = *(const ulonglong2*)(W1 + q * 4);
#pragma unroll
                    for (int i = 0; i < 4; i++) {
                        ulonglong2 hq = *(const ulonglong2*)(hc + (i << 9) + q * 4);
                        acc[0][i] = fma2(w0.x, hq.x, acc[0][i]);
                        acc[0][i] = fma2(w0.y, hq.y, acc[0][i]);
                        acc[1][i] = fma2(w1.x, hq.x, acc[1][i]);
                        acc[1][i] = fma2(w1.y, hq.y, acc[1][i]);
                    }
                }
            }

            // epilogue: store logits + per-batch argmax candidates
            const int vr0 = v0 + rp * 2;
            float bias0 = bp[vr0], bias1 = bp[vr0 + 1];
#pragma unroll
            for (int i = 0; i < 4; i++) {
                const int b = bq * 4 + i;
                u64 pk = 0ull;
                if (vact) {
                    float2 f0 = unpk(acc[0][i]);
                    float2 f1 = unpk(acc[1][i]);
                    float l0 = f0.x + f0.y + bias0;
                    float l1 = f1.x + f1.y + bias1;
                    float* ob = &out[((size_t)b * T + t) * (size_t)V + vr0];
                    __stcs(ob,     l0);
                    __stcs(ob + 1, l1);
                    // order-preserving encode; tie-break -> lowest v
                    unsigned u0 = __float_as_uint(l0);
                    u0 = (u0 & 0x80000000u) ? ~u0 : (u0 | 0x80000000u);
                    unsigned u1 = __float_as_uint(l1);
                    u1 = (u1 & 0x80000000u) ? ~u1 : (u1 | 0x80000000u);
                    u64 p0 = ((u64)u0 << 32) | (unsigned)(~vr0);
                    u64 p1 = ((u64)u1 << 32) | (unsigned)(~(vr0 + 1));
                    pk = (p0 > p1) ? p0 : p1;
                }
                // reduce across the 8 lanes sharing this bq (strides 4,8,16)
#pragma unroll
                for (int off = 4; off <= 16; off <<= 1) {
                    u64 q = __shfl_xor_sync(0xffffffffu, pk, off);
                    if (q > pk) pk = q;
                }
                if (lane < 4) s_best[lane * 4 + i][warp] = pk;   // lane==bq holds it
            }
            __syncthreads();
            if (tid < B) {
                u64 pk = s_best[tid][0];
#pragma unroll
                for (int w = 1; w < 16; w++) {
                    u64 q = s_best[tid][w];
                    if (q > pk) pk = q;
                }
                atomicMax(&g_amax[p][tid], pk);
            }
        }
        gbar(++target);
    }
}

// ---------------- launch ----------------
extern "C" void kernel_launch(void* const* d_in, const int* in_sizes, int n_in,
                              void* d_out, int out_size) {
    const float* x   = (const float*)d_in[0];
    const float* Wt  = (const float*)d_in[1];
    const float* bp  = (const float*)d_in[2];
    const float* Wih = (const float*)d_in[3];
    const float* Whh = (const float*)d_in[4];
    const float* bih = (const float*)d_in[5];
    const float* bhh = (const float*)d_in[6];
    float* out = (float*)d_out;

    const int T = out_size / (B * V);
    if (T <= 0) return;

    cudaFuncSetAttribute(decoder_kernel,
                         cudaFuncAttributeMaxDynamicSharedMemorySize, SMEM_BYTES);

    init_kernel<<<32, 256>>>();
    decoder_kernel<<<NBLK, NTHR, SMEM_BYTES>>>(x, Wt, bp, Wih, Whh, bih, bhh, out, T);
}

// round 16
// speedup vs baseline: 2.1404x; 2.1404x over previous
#include <cuda_runtime.h>
#include <cstdint>
#include <math.h>

#define B    16
#define H    512
#define V    32000
#define NL   2
#define NBLK 148           // persistent blocks (GB300: 148+ SMs), all co-resident
#define NLSTM_BLK 128      // LSTM j-map needs exactly 128 blocks
#define NTHR 512           // 16 warps/SM
#define ROWS_PER_BLK 217   // 148 * 217 = 32116 >= V (tail masked)
#define WCHUNK 32          // logits K-chunk (floats)
#define NCHUNK (H / WCHUNK)        // 16
#define WPADF  36          // padded row floats -> W row conflicts capped at width
#define WTILEF (ROWS_PER_BLK * WPADF)   // 7812 floats per buffer

typedef unsigned long long u64;

// dyn smem layout (floats):
//  LSTM : s_in = [0,8192), s_h = [8192,16384)
//  logit: h_s  = [0,8196) (4-float gap before batch 8), W_s = [16384, +2*7812)
#define DYN_FLOATS (16384 + 2 * WTILEF)
#define SMEM_BYTES (DYN_FLOATS * 4)

// ---------------- device state ----------------
__device__ float g_h[2][NL][B][H];     // ping-pong hidden state
__device__ u64 g_amax[2][B];           // double-buffered argmax accumulator
__device__ unsigned g_cnt;             // monotonic barrier counter

// ---------------- packed f32x2 helpers ----------------
__device__ __forceinline__ u64 fma2(u64 a, u64 b, u64 c) {
    u64 d; asm("fma.rn.f32x2 %0,%1,%2,%3;" : "=l"(d) : "l"(a), "l"(b), "l"(c));
    return d;
}
__device__ __forceinline__ u64 add2(u64 a, u64 b) {
    u64 d; asm("add.rn.f32x2 %0,%1,%2;" : "=l"(d) : "l"(a), "l"(b));
    return d;
}
__device__ __forceinline__ float2 unpk(u64 a) {
    float2 r; asm("mov.b64 {%0,%1},%2;" : "=f"(r.x), "=f"(r.y) : "l"(a));
    return r;
}
__device__ __forceinline__ float sigm(float x) { return 1.f / (1.f + expf(-x)); }

// ---------------- cp.async helpers ----------------
__device__ __forceinline__ void cpa16(uint32_t dst, const void* src) {
    asm volatile("cp.async.cg.shared.global [%0], [%1], 16;"
                 :: "r"(dst), "l"(src));
}
#define CP_COMMIT() asm volatile("cp.async.commit_group;")
#define CP_WAIT0()  asm volatile("cp.async.wait_group 0;")

// ---------------- grid barrier: release-add / acquire-spin, one address ----
__device__ __forceinline__ void gbar(unsigned target) {
    __syncthreads();
    if (threadIdx.x == 0) {
        asm volatile("red.release.gpu.global.add.u32 [%0], 1;"
                     :: "l"(&g_cnt) : "memory");
        const unsigned need = NBLK * target;
        unsigned v;
        for (;;) {
            asm volatile("ld.acquire.gpu.global.u32 %0, [%1];"
                         : "=r"(v) : "l"(&g_cnt) : "memory");
            if (v >= need) break;
            __nanosleep(64);                   // backoff: cut poll traffic
        }
    }
    __syncthreads();
}

// ---------------- init ----------------
__global__ void init_kernel() {
    int tid = blockIdx.x * blockDim.x + threadIdx.x;
    int stride = gridDim.x * blockDim.x;
    float* p = &g_h[0][0][0][0];
    for (int i = tid; i < 2 * NL * B * H; i += stride) p[i] = 0.f;
    if (blockIdx.x == 0 && threadIdx.x < 2 * B)
        (&g_amax[0][0])[threadIdx.x] = 0ull;
    if (blockIdx.x == 0 && threadIdx.x == 0) g_cnt = 0u;
}

// ---------------- persistent decoder ----------------
__global__ __launch_bounds__(NTHR, 1) void decoder_kernel(
    const float* __restrict__ x,   const float* __restrict__ Wt,
    const float* __restrict__ bp,  const float* __restrict__ Wih,
    const float* __restrict__ Whh, const float* __restrict__ bih,
    const float* __restrict__ bhh, float* __restrict__ out, int T)
{
    extern __shared__ __align__(16) float dyn[];
    __shared__ float s_part[2][2][4][4][8];   // [side][bhalf][jl][gate][b8]
    __shared__ u64 s_best[B][16];

    const int tid  = threadIdx.x;
    const int bx   = blockIdx.x;
    const int lane = tid & 31;
    const int warp = tid >> 5;

    // ---- LSTM role (blocks < 128): warp = (side, bhalf, jl) ----
    const int w_jl    = warp & 3;
    const int w_bh    = (warp >> 2) & 1;
    const int w_side  = warp >> 3;
    const int j       = bx * 4 + w_jl;        // valid when bx < NLSTM_BLK

    // ---- logits role: thread = (row, bhalf) ----
    const int v0       = bx * ROWS_PER_BLK;
    const int lrow_raw = tid >> 1;            // 0..255
    const bool vact    = (lrow_raw < ROWS_PER_BLK) && (v0 + lrow_raw < V);
    const int lrow  = (lrow_raw < ROWS_PER_BLK) ? lrow_raw : (ROWS_PER_BLK - 1);
    const int lbh   = tid & 1;
    const int v     = v0 + lrow;

    float* const s_in = dyn;                  // [16][512]
    float* const s_h  = dyn + 8192;           // [16][512]
    float* const h_s  = dyn;                  // [16][512] + gap (logits phase)
    float* const W_s  = dyn + 16384;          // [2][217][36]

    float c_reg[2] = {0.f, 0.f};              // cell state, fixed per thread
    unsigned target = 0;

#pragma unroll 1
    for (int t = 0; t < T; t++) {
        const int p = t & 1;                  // h read side; write side 1-p

        // ---- prefetch logits W chunk 0 NOW: hides its L2 latency under LSTM
        for (int idx = tid; idx < ROWS_PER_BLK * 8; idx += NTHR) {
            int row = idx >> 3, seg = idx & 7;
            int rg = v0 + row; if (rg > V - 1) rg = V - 1;   // OOB clamp
            cpa16((uint32_t)__cvta_generic_to_shared(
                      &W_s[row * WPADF + seg * 4]),
                  Wt + (size_t)rg * H + seg * 4);
        }
        CP_COMMIT();

        // ================= LSTM layers (blocks < 128) =================
#pragma unroll
        for (int layer = 0; layer < NL; layer++) {
            if (bx < NLSTM_BLK) {
                // ---- stage input + recurrent h for ALL 16 batches ----
                for (int i = tid; i < 2048; i += NTHR) {
                    int b = i >> 7, c4 = i & 127;
                    const float4* srcp;
                    if (layer == 0) {
                        if (t == 0) {
                            srcp = (const float4*)(x + (size_t)b * H) + c4;
                        } else {
                            u64 am;
                            asm volatile("ld.global.cg.u64 %0,[%1];"
                                         : "=l"(am) : "l"(&g_amax[1 - p][b])
                                         : "memory");
                            unsigned idx = ~(unsigned)am;
                            if (idx >= V) idx = 0;          // defensive
                            srcp = (const float4*)(Wt + (size_t)idx * H) + c4;
                        }
                    } else {
                        srcp = (const float4*)(&g_h[1 - p][0][b][0]) + c4;
                    }
                    ((float4*)s_in)[i] = __ldcg(srcp);
                    ((float4*)s_h)[i] =
                        __ldcg((const float4*)(&g_h[p][layer][b][0]) + c4);
                }
                __syncthreads();

                // ---- partial dot: 4 gates x 8 batches, one W-side per warp
                const float* Wsel = (w_side ? Whh : Wih) + (size_t)layer * 4 * H * H;
                const float* ssel = (w_side ? s_h : s_in) + (w_bh << 3) * H;

                u64 acc[4][8];
#pragma unroll
                for (int g = 0; g < 4; g++)
#pragma unroll
                    for (int b8 = 0; b8 < 8; b8++) acc[g][b8] = 0ull;

#pragma unroll
                for (int c = 0; c < 4; c++) {
                    const int koff = c * 128 + lane * 4;
                    ulonglong2 w0 = *(const ulonglong2*)(Wsel + (size_t)(0 * H + j) * H + koff);
                    ulonglong2 w1 = *(const ulonglong2*)(Wsel + (size_t)(1 * H + j) * H + koff);
                    ulonglong2 w2 = *(const ulonglong2*)(Wsel + (size_t)(2 * H + j) * H + koff);
                    ulonglong2 w3 = *(const ulonglong2*)(Wsel + (size_t)(3 * H + j) * H + koff);
#pragma unroll
                    for (int b8 = 0; b8 < 8; b8++) {
                        ulonglong2 sv = *(const ulonglong2*)(ssel + (b8 << 9) + koff);
                        acc[0][b8] = fma2(w0.x, sv.x, acc[0][b8]);
                        acc[0][b8] = fma2(w0.y, sv.y, acc[0][b8]);
                        acc[1][b8] = fma2(w1.x, sv.x, acc[1][b8]);
                        acc[1][b8] = fma2(w1.y, sv.y, acc[1][b8]);
                        acc[2][b8] = fma2(w2.x, sv.x, acc[2][b8]);
                        acc[2][b8] = fma2(w2.y, sv.y, acc[2][b8]);
                        acc[3][b8] = fma2(w3.x, sv.x, acc[3][b8]);
                        acc[3][b8] = fma2(w3.y, sv.y, acc[3][b8]);
                    }
                }
                // ---- warp tree reduce (lane 0 gets the k-sum) ----
#pragma unroll
                for (int off = 16; off >= 1; off >>= 1) {
#pragma unroll
                    for (int g = 0; g < 4; g++)
#pragma unroll
                        for (int b8 = 0; b8 < 8; b8++)
                            acc[g][b8] = add2(acc[g][b8],
                                __shfl_down_sync(0xffffffffu, acc[g][b8], off));
                }
                if (lane == 0) {
#pragma unroll
                    for (int g = 0; g < 4; g++)
#pragma unroll
                        for (int b8 = 0; b8 < 8; b8++) {
                            float2 f = unpk(acc[g][b8]);
                            s_part[w_side][w_bh][w_jl][g][b8] = f.x + f.y;
                        }
                }
                __syncthreads();

                // ---- activations: tid<64 owns cell (layer, b, j2) ----
                if (tid < 64) {
                    int b8a = tid & 7, jla = (tid >> 3) & 3, bha = tid >> 5;
                    int b  = bha * 8 + b8a;
                    int j2 = bx * 4 + jla;
                    const float* bi = bih + (size_t)layer * 4 * H;
                    const float* bh = bhh + (size_t)layer * 4 * H;
                    float gi = s_part[0][bha][jla][0][b8a] + s_part[1][bha][jla][0][b8a]
                             + bi[0 * H + j2] + bh[0 * H + j2];
                    float gf = s_part[0][bha][jla][1][b8a] + s_part[1][bha][jla][1][b8a]
                             + bi[1 * H + j2] + bh[1 * H + j2];
                    float gg = s_part[0][bha][jla][2][b8a] + s_part[1][bha][jla][2][b8a]
                             + bi[2 * H + j2] + bh[2 * H + j2];
                    float go = s_part[0][bha][jla][3][b8a] + s_part[1][bha][jla][3][b8a]
                             + bi[3 * H + j2] + bh[3 * H + j2];
                    float cn = sigm(gf) * c_reg[layer] + sigm(gi) * tanhf(gg);
                    float hn = sigm(go) * tanhf(cn);
                    c_reg[layer] = cn;
                    g_h[1 - p][layer][b][j2] = hn;
                }
            }
            gbar(++target);
        }

        // ================= logits + argmax (cp.async-pipelined W) ==========
        {
            // reset the OTHER amax slot for step t+1
            if (bx == 0 && tid < B) atomicExch(&g_amax[1 - p][tid], 0ull);

            // stage h1 [16][512] with a 4-float gap before batch 8:
            // the two lane-groups then hit disjoint bank windows -> no conflict
            const float4* hp = (const float4*)(&g_h[1 - p][1][0][0]);
            for (int i = tid; i < 2048; i += NTHR) {
                float* dst = h_s + (i << 2) + ((i >= 1024) ? 4 : 0);
                *(float4*)dst = __ldcg(hp + i);
            }

            u64 acc[8];
#pragma unroll
            for (int b8 = 0; b8 < 8; b8++) acc[b8] = 0ull;

            const float* hbase = h_s + (lbh << 3) * H + (lbh ? 4 : 0);

#pragma unroll 1
            for (int kc = 0; kc < NCHUNK; kc++) {
                CP_WAIT0();
                __syncthreads();                 // chunk kc visible; prev done
                if (kc + 1 < NCHUNK) {           // prefetch kc+1 -> other buf
                    float* Wn = W_s + ((kc + 1) & 1) * WTILEF;
                    const float* gsrc = Wt + (size_t)(kc + 1) * WCHUNK;
                    for (int idx = tid; idx < ROWS_PER_BLK * 8; idx += NTHR) {
                        int row = idx >> 3, seg = idx & 7;
                        int rg = v0 + row; if (rg > V - 1) rg = V - 1;
                        cpa16((uint32_t)__cvta_generic_to_shared(
                                  &Wn[row * WPADF + seg * 4]),
                              gsrc + (size_t)rg * H + seg * 4);
                    }
                }
                CP_COMMIT();

                const float* Wc = W_s + (kc & 1) * WTILEF + lrow * WPADF;
                const float* hc = hbase + kc * WCHUNK;
#pragma unroll
                for (int q = 0; q < 8; q++) {
                    ulonglong2 wq = *(const ulonglong2*)(Wc + q * 4);
#pragma unroll
                    for (int b8 = 0; b8 < 8; b8++) {
                        ulonglong2 hq = *(const ulonglong2*)(hc + (b8 << 9) + q * 4);
                        acc[b8] = fma2(wq.x, hq.x, acc[b8]);
                        acc[b8] = fma2(wq.y, hq.y, acc[b8]);
                    }
                }
            }

            const float bias = vact ? bp[v] : 0.f;
#pragma unroll
            for (int b8 = 0; b8 < 8; b8++) {
                u64 pk = 0ull;
                if (vact) {
                    float2 f = unpk(acc[b8]);
                    float logit = f.x + f.y + bias;
                    int b = lbh * 8 + b8;
                    __stcs(&out[((size_t)b * T + t) * (size_t)V + v], logit);
                    // order-preserving encode; tie-break -> lowest v
                    unsigned ub = __float_as_uint(logit);
                    ub = (ub & 0x80000000u) ? ~ub : (ub | 0x80000000u);
                    pk = ((u64)ub << 32) | (unsigned)(~v);
                }
                // reduce over same-parity lanes (16 rows of this warp)
#pragma unroll
                for (int off = 2; off <= 16; off <<= 1) {
                    u64 q = __shfl_xor_sync(0xffffffffu, pk, off);
                    if (q > pk) pk = q;
                }
                if (lane < 2) s_best[lane * 8 + b8][warp] = pk;  // lane0:bh0, lane1:bh1
            }
            __syncthreads();
            if (tid < B) {
                u64 pk = s_best[tid][0];
#pragma unroll
                for (int w = 1; w < 16; w++) {
                    u64 q = s_best[tid][w];
                    if (q > pk) pk = q;
                }
                atomicMax(&g_amax[p][tid], pk);
            }
        }
        gbar(++target);
    }
}

// ---------------- launch ----------------
extern "C" void kernel_launch(void* const* d_in, const int* in_sizes, int n_in,
                              void* d_out, int out_size) {
    const float* x   = (const float*)d_in[0];
    const float* Wt  = (const float*)d_in[1];
    const float* bp  = (const float*)d_in[2];
    const float* Wih = (const float*)d_in[3];
    const float* Whh = (const float*)d_in[4];
    const float* bih = (const float*)d_in[5];
    const float* bhh = (const float*)d_in[6];
    float* out = (float*)d_out;

    const int T = out_size / (B * V);
    if (T <= 0) return;

    cudaFuncSetAttribute(decoder_kernel,
                         cudaFuncAttributeMaxDynamicSharedMemorySize, SMEM_BYTES);

    init_kernel<<<32, 256>>>();
    decoder_kernel<<<NBLK, NTHR, SMEM_BYTES>>>(x, Wt, bp, Wih, Whh, bih, bhh, out, T);
}